// round 15
// baseline (speedup 1.0000x reference)
#include <cuda_runtime.h>
#include <cstdint>

// ---- shared memory layout (floats) ----
#define OFF_P    0        // 4 panel buffers x 2048 floats (8KB each), XOR-swizzled
#define OFF_A    8192     // 4096: A1 (mma B-operand); first 512 reused as layer3 partials
#define OFF_B2   12288    // 256  [0:128]=a [128:256]=b
#define OFF_W3   12544    // 1024 [0:512]=a [512:1024]=b
#define OFF_B3   13568    // 8
#define OFF_CS   13576    // 256
#define OFF_H    13960    // 96
#define OFF_SC2  14056    // 8
#define OFF_LG   14064    // 2
#define OFF_MB   14068    // 10 mbarriers x 8B
#define SMEM_FLOATS 14088
#define SMEM_BYTES (SMEM_FLOATS * 4)

#define SWZ(r) (((r) & 7) << 2)
// mbarriers: FULL b = MB(b), FREE b = MB(4+b), H1RDY = MB(8), A1RDY = MB(9)
#define MB(i) (mb + 8u * (i))

// exact GELU via A&S 7.1.26 erfc (|abs err| <= ~1.5e-7)
__device__ __forceinline__ float gelu_fast(float v) {
    float z = fabsf(v) * 0.7071067811865475f;
    float t;
    asm("rcp.approx.f32 %0, %1;" : "=f"(t) : "f"(fmaf(0.3275911f, z, 1.0f)));
    float e;
    asm("ex2.approx.f32 %0, %1;" : "=f"(e) : "f"(z * z * -1.4426950408889634f));
    float poly = fmaf(t, 1.061405429f, -1.453152027f);
    poly = fmaf(t, poly, 1.421413741f);
    poly = fmaf(t, poly, -0.284496736f);
    poly = fmaf(t, poly, 0.254829592f);
    float erfc_half = 0.5f * (poly * t) * e;
    float phi = 0.5f + copysignf(0.5f - erfc_half, v);
    return v * phi;
}

__device__ __forceinline__ float to_tf32(float x) {
    float r;
    asm("cvt.rna.tf32.f32 %0, %1;" : "=f"(r) : "f"(x));
    return r;
}
__device__ __forceinline__ float fast_tanh(float x) {
    float e;
    asm("ex2.approx.f32 %0, %1;" : "=f"(e) : "f"(x * 2.8853900817779268f));
    float r;
    asm("rcp.approx.f32 %0, %1;" : "=f"(r) : "f"(e + 1.0f));
    return fmaf(-2.0f, r, 1.0f);
}
__device__ __forceinline__ float fast_exp(float x) {
    float e;
    asm("ex2.approx.f32 %0, %1;" : "=f"(e) : "f"(x * 1.4426950408889634f));
    return e;
}

__device__ __forceinline__ void mma_tf32(float* c,
                                         uint32_t a0, uint32_t a1, uint32_t a2, uint32_t a3,
                                         uint32_t b0, uint32_t b1) {
    asm volatile(
        "mma.sync.aligned.m16n8k8.row.col.f32.tf32.tf32.f32 "
        "{%0,%1,%2,%3}, {%4,%5,%6,%7}, {%8,%9}, {%0,%1,%2,%3};"
        : "+f"(c[0]), "+f"(c[1]), "+f"(c[2]), "+f"(c[3])
        : "r"(a0), "r"(a1), "r"(a2), "r"(a3), "r"(b0), "r"(b1));
}

__device__ __forceinline__ void cp16(float* s, const float* g) {
    unsigned a = (unsigned)__cvta_generic_to_shared(s);
    asm volatile("cp.async.cg.shared.global [%0], [%1], 16;" :: "r"(a), "l"(g));
}

__device__ __forceinline__ void mbar_init(uint32_t a, uint32_t cnt) {
    asm volatile("mbarrier.init.shared.b64 [%0], %1;" :: "r"(a), "r"(cnt) : "memory");
}
__device__ __forceinline__ void mbar_arrive(uint32_t a) {
    asm volatile("mbarrier.arrive.shared.b64 _, [%0];" :: "r"(a) : "memory");
}
__device__ __forceinline__ void mbar_wait(uint32_t a, uint32_t par) {
    asm volatile(
        "{\n\t"
        ".reg .pred P1;\n"
        "WL%=:\n\t"
        "mbarrier.try_wait.parity.acquire.cta.shared::cta.b64 P1, [%0], %1, 0x989680;\n\t"
        "@P1 bra WD%=;\n\t"
        "bra.uni WL%=;\n"
        "WD%=:\n\t"
        "}"
        :: "r"(a), "r"(par) : "memory");
}
#define CBAR() asm volatile("bar.sync 5, 128;" ::: "memory")
#define ARRV(i) asm volatile("cp.async.mbarrier.arrive.noinc.shared.b64 [%0];" :: "r"(MB(i)) : "memory")

__global__ void __launch_bounds__(256, 4)
patchflow_kernel(const float* __restrict__ x, const float* __restrict__ pos,
                 const float* __restrict__ w1a, const float* __restrict__ b1a,
                 const float* __restrict__ w2a, const float* __restrict__ b2a,
                 const float* __restrict__ w3a, const float* __restrict__ b3a,
                 const float* __restrict__ gsa, const float* __restrict__ goa,
                 const int* __restrict__ pma,
                 const float* __restrict__ w1b, const float* __restrict__ b1b,
                 const float* __restrict__ w2b, const float* __restrict__ b2b,
                 const float* __restrict__ w3b, const float* __restrict__ b3b,
                 const float* __restrict__ gsb, const float* __restrict__ gob,
                 const int* __restrict__ pmb,
                 float* __restrict__ zout, float* __restrict__ ldjout)
{
    extern __shared__ float sm[];
    const int p = blockIdx.x;
    const int t = threadIdx.x;
    const int w = t >> 5, l = t & 31;

    float* As  = sm + OFF_A;
    float* B2s = sm + OFF_B2;
    float* W3s = sm + OFF_W3;
    float* B3s = sm + OFF_B3;
    float* CSs = sm + OFF_CS;
    float* Hs  = sm + OFF_H;
    float* SC2 = sm + OFF_SC2;
    float* LGs = sm + OFF_LG;
    const uint32_t mb = (uint32_t)__cvta_generic_to_shared(sm + OFF_MB);

    const float* w2aP = w2a + (size_t)p * 16384;
    const float* w2bP = w2b + (size_t)p * 16384;

    // producer copy geometry (t>=128): 16-row panel, 4 cp.async/thread
    const int wrow = w & 3;            // row group 0..3
    const int co = 4 * l;              // float4 col offset

    // panel G (0..15): buffer G&3, source rows (G&7)*16 + i, i = wrow+4k
    #define ISSUE(G) {                                                                 \
        const float* w2P_ = ((G) < 8) ? w2aP : w2bP;                                   \
        float* buf = sm + OFF_P + ((G) & 3) * 2048;                                    \
        _Pragma("unroll")                                                              \
        for (int k = 0; k < 4; k++) {                                                  \
            int i = wrow + 4 * k;                                                      \
            cp16(buf + i * 128 + (co ^ SWZ(i)),                                        \
                 w2P_ + (size_t)(((G) & 7) * 16 + i) * 128 + co);                      \
        } }

    if (t == 0) {
        #pragma unroll
        for (int i = 0; i < 10; i++) mbar_init(MB(i), 128);
    }
    __syncthreads();   // mbarrier init visible before any async arrival can fire

    // kick off panels 0-3 immediately (overlaps all prologue work)
    if (t >= 128) {
        ISSUE(0) ARRV(0);
        ISSUE(1) ARRV(1);
        ISSUE(2) ARRV(2);
        ISSUE(3) ARRV(3);
    }

    // ---- small weights into smem ----
    if (t < 128) {
        B2s[t]       = __ldg(b2a + (size_t)p * 128 + t);
        B2s[128 + t] = __ldg(b2b + (size_t)p * 128 + t);
        *(float4*)(W3s + 4 * t) = __ldg((const float4*)(w3a + (size_t)p * 512) + t);
    } else {
        *(float4*)(W3s + 512 + 4 * (t - 128)) =
            __ldg((const float4*)(w3b + (size_t)p * 512) + (t - 128));
    }
    if (t == 32) {
        *(float4*)(B3s)     = __ldg((const float4*)(b3a + (size_t)p * 4));
        *(float4*)(B3s + 4) = __ldg((const float4*)(b3b + (size_t)p * 4));
    }

    // ---- per-block coupling scales ----
    if (t == 96 || t == 97) {
        int blk = t - 96;
        const float* gsP = (blk ? gsb : gsa) + (size_t)p * 3;
        float lg = 0.f;
        #pragma unroll
        for (int c = 0; c < 3; c++) {
            float y = 0.5f * __ldg(gsP + c);
            float sc = 0.2f * ((y > 15.f) ? y : log1pf(expf(y)));
            SC2[blk * 3 + c] = sc;
            lg += logf(sc);
        }
        LGs[blk] = lg;
    }

    // ---- 3x3 stride-2 avg pool ----
    if (t < 96) {
        int b = t / 3, c = t % 3;
        int ph = p >> 6, pw = p & 63;
        const float* xp = x + (size_t)(b * 3 + c) * 16384;
        int y0 = 2 * ph - 1, x0 = 2 * pw - 1;
        float acc = 0.f;
        #pragma unroll
        for (int dy = 0; dy < 3; dy++) {
            int yy = y0 + dy;
            if (yy < 0) continue;
            #pragma unroll
            for (int dx = 0; dx < 3; dx++) {
                int xx = x0 + dx;
                if (xx < 0) continue;
                acc += __ldg(xp + yy * 128 + xx);
            }
        }
        Hs[t] = acc * (1.f / 9.f);
    }

    // ---- cond-sums for BOTH blocks ----
    {
        int o = t & 127;
        const float* w1P = ((t < 128) ? w1a : w1b) + (size_t)p * 2176;
        const float* b1P = ((t < 128) ? b1a : b1b) + (size_t)p * 128;
        const float* posP = pos + (size_t)p * 16;
        float cs = __ldg(b1P + o);
        #pragma unroll
        for (int k = 0; k < 16; k++)
            cs = fmaf(__ldg(posP + k), __ldg(w1P + (1 + k) * 128 + o), cs);
        CSs[t] = cs;
    }
    __syncthreads();

    // ---- layer 1 (block a), all 256 threads ----
    {
        const float* w1r0 = w1a + (size_t)p * 2176;
        float4 w1v = __ldg((const float4*)(w1r0) + l);
        float4 csv = *(const float4*)(CSs + 4 * l);
        #pragma unroll
        for (int r = 0; r < 4; r++) {
            int b = w + 8 * r;
            float h = Hs[b * 3];
            float4 v;
            v.x = to_tf32(gelu_fast(fmaf(h, w1v.x, csv.x)));
            v.y = to_tf32(gelu_fast(fmaf(h, w1v.y, csv.y)));
            v.z = to_tf32(gelu_fast(fmaf(h, w1v.z, csv.z)));
            v.w = to_tf32(gelu_fast(fmaf(h, w1v.w, csv.w)));
            *(float4*)(As + b * 128 + ((4 * l) ^ SWZ(b))) = v;
        }
    }
    __syncthreads();   // A1(blk a) visible; ROLES DIVERGE

    if (t >= 128) {
        // ===== PRODUCER: depth-4 cp.async pipeline, FREE-gated only =====
        mbar_wait(MB(4), 0u); ISSUE(4) ARRV(0);
        mbar_wait(MB(5), 0u); ISSUE(5) ARRV(1);
        mbar_wait(MB(6), 0u); ISSUE(6) ARRV(2);
        mbar_wait(MB(7), 0u); ISSUE(7) ARRV(3);
        mbar_wait(MB(4), 1u); ISSUE(8) ARRV(0);
        mbar_wait(MB(5), 1u); ISSUE(9) ARRV(1);
        mbar_wait(MB(6), 1u); ISSUE(10) ARRV(2);
        mbar_wait(MB(7), 1u); ISSUE(11) ARRV(3);

        // layer 1 for block b (As free after consumers' H1RDY)
        mbar_wait(MB(8), 0u);
        {
            const float* w1r0 = w1b + (size_t)p * 2176;
            int li = t & 31, bw = (t >> 5) & 3;
            float4 w1v = __ldg((const float4*)(w1r0) + li);
            float4 csv = *(const float4*)(CSs + 128 + 4 * li);
            #pragma unroll
            for (int r = 0; r < 8; r++) {
                int b = bw + 4 * r;
                float h = Hs[b * 3];
                float4 v;
                v.x = to_tf32(gelu_fast(fmaf(h, w1v.x, csv.x)));
                v.y = to_tf32(gelu_fast(fmaf(h, w1v.y, csv.y)));
                v.z = to_tf32(gelu_fast(fmaf(h, w1v.z, csv.z)));
                v.w = to_tf32(gelu_fast(fmaf(h, w1v.w, csv.w)));
                *(float4*)(As + b * 128 + ((4 * li) ^ SWZ(b))) = v;
            }
        }
        mbar_arrive(MB(9));   // A1(blk b) ready

        mbar_wait(MB(4), 0u); ISSUE(12) ARRV(0);
        mbar_wait(MB(5), 0u); ISSUE(13) ARRV(1);
        mbar_wait(MB(6), 0u); ISSUE(14) ARRV(2);
        mbar_wait(MB(7), 0u); ISSUE(15) ARRV(3);
    } else {
        // ===== CONSUMER (warps 0-3) =====
        const int gid = l >> 2, tig = l & 3;
        const int obase = w << 5;
        const int g0 = gid & 1, g1 = (gid >> 1) & 1;
        const int xbase = (gid >> 2) << 4;            // 16*g2: panel-base flip
        // in-panel A offsets: physical = row*128 + panel_base + oA[delta][j]
        int oA0[2], oA1[2];
        #pragma unroll
        for (int j = 0; j < 2; j++) {
            oA0[j] = 8 * (j ^ g1) + 4 * g0 + tig;
            oA1[j] = 8 * (j ^ g1) + 4 * (g0 ^ 1) + tig;
        }
        const int bsw0 = SWZ(tig), bsw1 = SWZ(tig + 4);
        int bo0[4], bo1[4];
        #pragma unroll
        for (int nt = 0; nt < 4; nt++) {
            int oo = obase + nt * 8 + gid;
            bo0[nt] = oo ^ bsw0;
            bo1[nt] = oo ^ bsw1;
        }
        float ldj = 0.f;   // valid for t<32

        for (int blk = 0; blk < 2; blk++) {
            if (blk == 1) mbar_wait(MB(9), 0u);

            float acc[2][4][4];
            #pragma unroll
            for (int mh = 0; mh < 2; mh++)
                #pragma unroll
                for (int nt = 0; nt < 4; nt++)
                    #pragma unroll
                    for (int k = 0; k < 4; k++) acc[mh][nt][k] = 0.f;

            #pragma unroll
            for (int pq = 0; pq < 8; pq++) {
                int g = blk * 8 + pq, bb = g & 3;
                mbar_wait(MB(bb), (uint32_t)((g >> 2) & 1));   // panel full
                const float* Pc = sm + OFF_P + bb * 2048;
                const float* Ac = As + ((pq << 4) ^ xbase);
                #pragma unroll
                for (int j = 0; j < 2; j++) {
                    uint32_t a00 = __float_as_uint(Ac[gid * 128 + oA0[j]]);
                    uint32_t a01 = __float_as_uint(Ac[(gid + 8) * 128 + oA0[j]]);
                    uint32_t a02 = __float_as_uint(Ac[gid * 128 + oA1[j]]);
                    uint32_t a03 = __float_as_uint(Ac[(gid + 8) * 128 + oA1[j]]);
                    uint32_t a10 = __float_as_uint(Ac[(gid + 16) * 128 + oA0[j]]);
                    uint32_t a11 = __float_as_uint(Ac[(gid + 24) * 128 + oA0[j]]);
                    uint32_t a12 = __float_as_uint(Ac[(gid + 16) * 128 + oA1[j]]);
                    uint32_t a13 = __float_as_uint(Ac[(gid + 24) * 128 + oA1[j]]);
                    const float* Brow0 = Pc + (j * 8 + tig) * 128;
                    const float* Brow1 = Brow0 + 512;
                    #pragma unroll
                    for (int nt = 0; nt < 4; nt++) {
                        uint32_t b0 = __float_as_uint(Brow0[bo0[nt]]);
                        uint32_t b1 = __float_as_uint(Brow1[bo1[nt]]);
                        mma_tf32(acc[0][nt], a00, a01, a02, a03, b0, b1);
                        mma_tf32(acc[1][nt], a10, a11, a12, a13, b0, b1);
                    }
                }
                mbar_arrive(MB(4 + bb));     // panel free
            }
            CBAR();                          // consumers done reading A1

            // ---- fused: bias + gelu + layer3 partial dot ----
            float4 ps0 = {0,0,0,0}, ps1 = ps0, ps2 = ps0, ps3 = ps0;
            {
                const float* B2 = B2s + blk * 128;
                const float* W3c = W3s + blk * 512;
                #pragma unroll
                for (int nt = 0; nt < 4; nt++) {
                    int colo = obase + nt * 8 + 2 * tig;
                    float4 wl = *(const float4*)(W3c + colo * 4);
                    float4 wh = *(const float4*)(W3c + colo * 4 + 4);
                    float bl = B2[colo], bh = B2[colo + 1];
                    float g;
                    #define ACC4(PS, G) { PS.x = fmaf(G, wl.x, PS.x); PS.y = fmaf(G, wl.y, PS.y); \
                                          PS.z = fmaf(G, wl.z, PS.z); PS.w = fmaf(G, wl.w, PS.w); }
                    #define ACC4H(PS, G) { PS.x = fmaf(G, wh.x, PS.x); PS.y = fmaf(G, wh.y, PS.y); \
                                           PS.z = fmaf(G, wh.z, PS.z); PS.w = fmaf(G, wh.w, PS.w); }
                    g = gelu_fast(acc[0][nt][0] + bl); ACC4(ps0, g)
                    g = gelu_fast(acc[0][nt][1] + bh); ACC4H(ps0, g)
                    g = gelu_fast(acc[0][nt][2] + bl); ACC4(ps1, g)
                    g = gelu_fast(acc[0][nt][3] + bh); ACC4H(ps1, g)
                    g = gelu_fast(acc[1][nt][0] + bl); ACC4(ps2, g)
                    g = gelu_fast(acc[1][nt][1] + bh); ACC4H(ps2, g)
                    g = gelu_fast(acc[1][nt][2] + bl); ACC4(ps3, g)
                    g = gelu_fast(acc[1][nt][3] + bh); ACC4H(ps3, g)
                    #undef ACC4
                    #undef ACC4H
                }
            }
            #define RED(PS) { \
                PS.x += __shfl_xor_sync(0xffffffffu, PS.x, 1); PS.x += __shfl_xor_sync(0xffffffffu, PS.x, 2); \
                PS.y += __shfl_xor_sync(0xffffffffu, PS.y, 1); PS.y += __shfl_xor_sync(0xffffffffu, PS.y, 2); \
                PS.z += __shfl_xor_sync(0xffffffffu, PS.z, 1); PS.z += __shfl_xor_sync(0xffffffffu, PS.z, 2); \
                PS.w += __shfl_xor_sync(0xffffffffu, PS.w, 1); PS.w += __shfl_xor_sync(0xffffffffu, PS.w, 2); }
            RED(ps0) RED(ps1) RED(ps2) RED(ps3)
            #undef RED
            if (tig == 0) {
                float* A3P = As + w * 128;
                *(float4*)(A3P + gid * 4)        = ps0;
                *(float4*)(A3P + (gid + 8) * 4)  = ps1;
                *(float4*)(A3P + (gid + 16) * 4) = ps2;
                *(float4*)(A3P + (gid + 24) * 4) = ps3;
            }
            CBAR();                          // partials visible

            // ---- coupling (folds final cross-warp A3 reduction in) ----
            if (t < 32) {
                int b = t;
                float a3[4];
                #pragma unroll
                for (int j = 0; j < 4; j++) {
                    float s = As[b * 4 + j] + As[128 + b * 4 + j]
                            + As[256 + b * 4 + j] + As[384 + b * 4 + j];
                    a3[j] = (s + B3s[blk * 4 + j]) * 0.1f;
                }
                const float* goP = (blk ? gob : goa) + (size_t)p * 3;
                const int*   pmP = (blk ? pmb : pma) + (size_t)p * 3;
                float sc0 = SC2[blk * 3], sc1 = SC2[blk * 3 + 1], sc2 = SC2[blk * 3 + 2];
                float s0 = 2.f * fast_tanh(a3[0]);
                float s1 = 2.f * fast_tanh(a3[1]);
                float ov0 = Hs[b * 3];
                float ov1 = Hs[b * 3 + 1] * fast_exp(s0) + a3[2];
                float ov2 = Hs[b * 3 + 2] * fast_exp(s1) + a3[3];
                ov0 = ov0 * sc0 + __ldg(goP);
                ov1 = ov1 * sc1 + __ldg(goP + 1);
                ov2 = ov2 * sc2 + __ldg(goP + 2);
                ldj += s0 + s1 + LGs[blk];
                int k0 = __ldg(pmP), k1 = __ldg(pmP + 1), k2 = __ldg(pmP + 2);
                Hs[b * 3 + 0] = (k0 == 0) ? ov0 : ((k0 == 1) ? ov1 : ov2);
                Hs[b * 3 + 1] = (k1 == 0) ? ov0 : ((k1 == 1) ? ov1 : ov2);
                Hs[b * 3 + 2] = (k2 == 0) ? ov0 : ((k2 == 1) ? ov1 : ov2);
            }
            CBAR();                          // Hs visible among consumers
            if (blk == 0) mbar_arrive(MB(8));   // H ready -> producers layer1(blk b)
        }

        if (t < 96) zout[(size_t)p * 96 + t] = Hs[t];
        if (t < 32) ldjout[(size_t)p * 32 + t] = ldj;
    }
    #undef ISSUE
}

extern "C" void kernel_launch(void* const* d_in, const int* in_sizes, int n_in,
                              void* d_out, int out_size) {
    (void)n_in; (void)out_size;

    int ia[9], ib[9];
    if (in_sizes[10] == 12288) {
        const int A[9]  = {2, 3, 4, 5, 6, 7, 8, 9, 10};
        const int Bn[9] = {11, 12, 13, 14, 15, 16, 17, 18, 19};
        for (int i = 0; i < 9; i++) { ia[i] = A[i]; ib[i] = Bn[i]; }
    } else {
        const int A[9]  = {2, 3, 4, 5, 6, 7, 8, 9, 18};
        const int Bn[9] = {10, 11, 12, 13, 14, 15, 16, 17, 19};
        for (int i = 0; i < 9; i++) { ia[i] = A[i]; ib[i] = Bn[i]; }
    }

    cudaFuncSetAttribute(patchflow_kernel,
                         cudaFuncAttributeMaxDynamicSharedMemorySize, SMEM_BYTES);

    float* z = (float*)d_out;                 // [4096, 32, 3]
    float* ldj = z + (size_t)4096 * 32 * 3;   // [4096, 32]

    patchflow_kernel<<<4096, 256, SMEM_BYTES>>>(
        (const float*)d_in[0], (const float*)d_in[1],
        (const float*)d_in[ia[0]], (const float*)d_in[ia[1]],
        (const float*)d_in[ia[2]], (const float*)d_in[ia[3]],
        (const float*)d_in[ia[4]], (const float*)d_in[ia[5]],
        (const float*)d_in[ia[6]], (const float*)d_in[ia[7]],
        (const int*)d_in[ia[8]],
        (const float*)d_in[ib[0]], (const float*)d_in[ib[1]],
        (const float*)d_in[ib[2]], (const float*)d_in[ib[3]],
        (const float*)d_in[ib[4]], (const float*)d_in[ib[5]],
        (const float*)d_in[ib[6]], (const float*)d_in[ib[7]],
        (const int*)d_in[ib[8]],
        z, ldj);
}